// round 1
// baseline (speedup 1.0000x reference)
#include <cuda_runtime.h>
#include <cuda_bf16.h>
#include <cstdint>

#define BT 2048
#define TT 64
#define CCH 768
#define NK 192
#define KCH 64
#define NCHUNK 12
#define BPB 2

// smem layout (bytes):
// projection phase: XH [128][72] bf16 @0 (18432), XL @18432 (18432),
//                   W double buffers @36864: per buf 51200 (hi 25600 + lo 25600) -> total 139264
// attention phase (reuses same allocation):
//   KS @0, QS @33280, VS @66560, PS @99840  (each 2*64*65 floats = 33280 B)
#define SMEM_BYTES 139264

__device__ __align__(16) __nv_bfloat16 g_Whi[CCH * NK];
__device__ __align__(16) __nv_bfloat16 g_Wlo[CCH * NK];

__global__ void prep_weights(const float* __restrict__ Wk,
                             const float* __restrict__ Wq,
                             const float* __restrict__ Wv) {
    int i = blockIdx.x * blockDim.x + threadIdx.x;
    if (i >= CCH * NK) return;
    int c = i / NK, n = i % NK;
    float w = (n < 64) ? Wk[c * 64 + n] : (n < 128) ? Wq[c * 64 + (n - 64)] : Wv[c * 64 + (n - 128)];
    __nv_bfloat16 hi = __float2bfloat16(w);
    g_Whi[i] = hi;
    g_Wlo[i] = __float2bfloat16(w - __bfloat162float(hi));
}

__device__ __forceinline__ uint32_t sptr(const void* p) {
    return (uint32_t)__cvta_generic_to_shared(p);
}
__device__ __forceinline__ void ldsm_x4(uint32_t* r, uint32_t addr) {
    asm volatile("ldmatrix.sync.aligned.m8n8.x4.shared.b16 {%0,%1,%2,%3}, [%4];"
                 : "=r"(r[0]), "=r"(r[1]), "=r"(r[2]), "=r"(r[3]) : "r"(addr));
}
__device__ __forceinline__ void ldsm_x2t(uint32_t* r, uint32_t addr) {
    asm volatile("ldmatrix.sync.aligned.m8n8.x2.trans.shared.b16 {%0,%1}, [%2];"
                 : "=r"(r[0]), "=r"(r[1]) : "r"(addr));
}
__device__ __forceinline__ void mma16816(float* c, const uint32_t* a, const uint32_t* b) {
    asm volatile("mma.sync.aligned.m16n8k16.row.col.f32.bf16.bf16.f32 "
                 "{%0,%1,%2,%3}, {%4,%5,%6,%7}, {%8,%9}, {%0,%1,%2,%3};"
                 : "+f"(c[0]), "+f"(c[1]), "+f"(c[2]), "+f"(c[3])
                 : "r"(a[0]), "r"(a[1]), "r"(a[2]), "r"(a[3]), "r"(b[0]), "r"(b[1]));
}
__device__ __forceinline__ void cpasync16(uint32_t daddr, const void* src) {
    asm volatile("cp.async.cg.shared.global [%0], [%1], 16;" :: "r"(daddr), "l"(src));
}

extern "C" __global__ void __launch_bounds__(256, 1)
head_main(const float* __restrict__ x, float* __restrict__ out) {
    extern __shared__ char smem[];
    __nv_bfloat16* XH = (__nv_bfloat16*)(smem);
    __nv_bfloat16* XL = (__nv_bfloat16*)(smem + 18432);

    const int tid = threadIdx.x;
    const int w = tid >> 5;
    const int lane = tid & 31;
    const int b0 = blockIdx.x * BPB;

    // -------- x register-prefetch mapping: each thread owns 32 floats of a chunk
    const int xr_row = tid >> 1;            // 0..127  (row within the 2-batch tile)
    const int xr_c0 = (tid & 1) * 32;       // half-row
    const float* xbase = x + ((size_t)(b0 + (xr_row >> 6)) * TT + (xr_row & 63)) * CCH + xr_c0;

    float4 xr[8];
#pragma unroll
    for (int i = 0; i < 8; i++) xr[i] = *(const float4*)(xbase + 0 * KCH + i * 4);

    // -------- issue W chunk 0 -> buf 0 (cp.async, bf16 hi+lo, pad 200)
    {
#pragma unroll
        for (int j = 0; j < 6; j++) {
            int idx = tid * 6 + j;             // 0..1535 ; 24 uint4 per 192-col row
            int row = idx / 24, c16 = (idx % 24) * 8;
            __nv_bfloat16* dh = (__nv_bfloat16*)(smem + 36864) + row * 200 + c16;
            __nv_bfloat16* dl = dh + 12800;    // +25600 bytes
            cpasync16(sptr(dh), g_Whi + row * 192 + c16);
            cpasync16(sptr(dl), g_Wlo + row * 192 + c16);
        }
        asm volatile("cp.async.commit_group;");
    }

    float acc[24][4];
#pragma unroll
    for (int nt = 0; nt < 24; nt++)
#pragma unroll
        for (int r = 0; r < 4; r++) acc[nt][r] = 0.0f;

    const int a_off = (16 * w + (lane & 15)) * 72 + (lane >> 4) * 8;  // A ldmatrix base (elems)
    const int b_lrow = (lane & 15);

#pragma unroll 1
    for (int kc = 0; kc < NCHUNK; kc++) {
        const int buf = kc & 1;
        __syncthreads();  // all mma of chunk kc-1 done: safe to overwrite XH/XL and W[buf^1]

        if (kc + 1 < NCHUNK) {
            const int kn = kc + 1;
#pragma unroll
            for (int j = 0; j < 6; j++) {
                int idx = tid * 6 + j;
                int row = idx / 24, c16 = (idx % 24) * 8;
                __nv_bfloat16* dh = (__nv_bfloat16*)(smem + 36864 + (buf ^ 1) * 51200) + row * 200 + c16;
                __nv_bfloat16* dl = dh + 12800;
                cpasync16(sptr(dh), g_Whi + (size_t)kn * KCH * NK + row * 192 + c16);
                cpasync16(sptr(dl), g_Wlo + (size_t)kn * KCH * NK + row * 192 + c16);
            }
            asm volatile("cp.async.commit_group;");
        }

        // convert current x regs -> XH/XL smem (hi/lo split)
        {
            const int base = xr_row * 72 + xr_c0;
#pragma unroll
            for (int i = 0; i < 8; i++) {
                float4 v = xr[i];
                __nv_bfloat16 h0 = __float2bfloat16(v.x), h1 = __float2bfloat16(v.y);
                __nv_bfloat16 h2 = __float2bfloat16(v.z), h3 = __float2bfloat16(v.w);
                __nv_bfloat16 l0 = __float2bfloat16(v.x - __bfloat162float(h0));
                __nv_bfloat16 l1 = __float2bfloat16(v.y - __bfloat162float(h1));
                __nv_bfloat16 l2 = __float2bfloat16(v.z - __bfloat162float(h2));
                __nv_bfloat16 l3 = __float2bfloat16(v.w - __bfloat162float(h3));
                __nv_bfloat162 p;
                p.x = h0; p.y = h1; *(__nv_bfloat162*)(XH + base + i * 4) = p;
                p.x = h2; p.y = h3; *(__nv_bfloat162*)(XH + base + i * 4 + 2) = p;
                p.x = l0; p.y = l1; *(__nv_bfloat162*)(XL + base + i * 4) = p;
                p.x = l2; p.y = l3; *(__nv_bfloat162*)(XL + base + i * 4 + 2) = p;
            }
        }

        if (kc + 1 < NCHUNK) asm volatile("cp.async.wait_group 1;");
        else                 asm volatile("cp.async.wait_group 0;");
        __syncthreads();  // XH/XL + W[buf] ready for everyone

        // prefetch next x chunk into registers (consumed next iteration)
        if (kc + 1 < NCHUNK) {
#pragma unroll
            for (int i = 0; i < 8; i++) xr[i] = *(const float4*)(xbase + (kc + 1) * KCH + i * 4);
        }

        const __nv_bfloat16* WHs = (const __nv_bfloat16*)(smem + 36864 + buf * 51200);
        const __nv_bfloat16* WLs = WHs + 12800;

#pragma unroll
        for (int ks = 0; ks < 4; ks++) {
            uint32_t ah[4], al[4];
            ldsm_x4(ah, sptr(XH + a_off + ks * 16));
            ldsm_x4(al, sptr(XL + a_off + ks * 16));
            const int brow = (ks * 16 + b_lrow) * 200;
#pragma unroll
            for (int nt = 0; nt < 24; nt++) {
                uint32_t bh[2], bl[2];
                ldsm_x2t(bh, sptr(WHs + brow + nt * 8));
                ldsm_x2t(bl, sptr(WLs + brow + nt * 8));
                mma16816(acc[nt], ah, bh);
                mma16816(acc[nt], ah, bl);
                mma16816(acc[nt], al, bh);
            }
        }
    }
    __syncthreads();  // projection done; smem is repurposed

    // -------- write KQV fragments to smem (pad 65 floats per row)
    float* KS = (float*)smem;
    float* QS = KS + 8320;   // 2*64*65
    float* VS = QS + 8320;
    float* PS = VS + 8320;

    const int bb = w >> 2;                       // batch within block
    const int t0 = (w & 3) * 16 + (lane >> 2);   // token row
    const int c2 = (lane & 3) * 2;
#pragma unroll
    for (int nt = 0; nt < 24; nt++) {
        int col = nt * 8 + c2;
        float* dst = (col < 64) ? KS : (col < 128) ? QS : VS;
        int cc = col & 63;
        float* p0 = dst + bb * 4160 + t0 * 65 + cc;
        p0[0] = acc[nt][0];
        p0[1] = acc[nt][1];
        p0[8 * 65] = acc[nt][2];
        p0[8 * 65 + 1] = acc[nt][3];
    }
    __syncthreads();

    // -------- S = q k^T * 0.125, causal softmax (fp32, microtile 4 rows x 8 cols per lane)
    const int li = lane >> 3, lj = lane & 7;
    const int i0 = (w & 3) * 16;
    const float* qrow = QS + bb * 4160;
    const float* krow = KS + bb * 4160;

    float s[4][8];
#pragma unroll
    for (int t = 0; t < 4; t++)
#pragma unroll
        for (int m = 0; m < 8; m++) s[t][m] = 0.0f;

#pragma unroll 4
    for (int c = 0; c < 64; c++) {
        float qv[4], kv[8];
#pragma unroll
        for (int t = 0; t < 4; t++) qv[t] = qrow[(i0 + li + 4 * t) * 65 + c];
#pragma unroll
        for (int m = 0; m < 8; m++) kv[m] = krow[(lj + 8 * m) * 65 + c];
#pragma unroll
        for (int t = 0; t < 4; t++)
#pragma unroll
            for (int m = 0; m < 8; m++) s[t][m] += qv[t] * kv[m];
    }

#pragma unroll
    for (int t = 0; t < 4; t++) {
        const int row = i0 + li + 4 * t;
        float mt = -3.0e38f;
#pragma unroll
        for (int m = 0; m < 8; m++) {
            int col = lj + 8 * m;
            float v = s[t][m] * 0.125f;
            v = (col <= row) ? v : -3.0e38f;
            s[t][m] = v;
            mt = fmaxf(mt, v);
        }
        mt = fmaxf(mt, __shfl_xor_sync(0xffffffffu, mt, 1));
        mt = fmaxf(mt, __shfl_xor_sync(0xffffffffu, mt, 2));
        mt = fmaxf(mt, __shfl_xor_sync(0xffffffffu, mt, 4));
        float sum = 0.0f;
#pragma unroll
        for (int m = 0; m < 8; m++) {
            float e = __expf(s[t][m] - mt);
            s[t][m] = e;
            sum += e;
        }
        sum += __shfl_xor_sync(0xffffffffu, sum, 1);
        sum += __shfl_xor_sync(0xffffffffu, sum, 2);
        sum += __shfl_xor_sync(0xffffffffu, sum, 4);
        float inv = 1.0f / sum;
#pragma unroll
        for (int m = 0; m < 8; m++)
            PS[bb * 4160 + row * 65 + lj + 8 * m] = s[t][m] * inv;
    }
    __syncthreads();

    // -------- out = P @ v (fp32 microtile)
    float o[4][8];
#pragma unroll
    for (int t = 0; t < 4; t++)
#pragma unroll
        for (int m = 0; m < 8; m++) o[t][m] = 0.0f;

    const float* prow = PS + bb * 4160;
    const float* vrow = VS + bb * 4160;
#pragma unroll 4
    for (int cs = 0; cs < 64; cs++) {
        float pv[4], vv[8];
#pragma unroll
        for (int t = 0; t < 4; t++) pv[t] = prow[(i0 + li + 4 * t) * 65 + cs];
#pragma unroll
        for (int m = 0; m < 8; m++) vv[m] = vrow[cs * 65 + lj + 8 * m];
#pragma unroll
        for (int t = 0; t < 4; t++)
#pragma unroll
            for (int m = 0; m < 8; m++) o[t][m] += pv[t] * vv[m];
    }
    __syncthreads();  // all PS reads done -> reuse region as output staging

    float* OS = PS;  // [2][64][64] packed
#pragma unroll
    for (int t = 0; t < 4; t++)
#pragma unroll
        for (int m = 0; m < 8; m++)
            OS[bb * 4096 + (i0 + li + 4 * t) * 64 + lj + 8 * m] = o[t][m];
    __syncthreads();

    float4* og = (float4*)(out + (size_t)b0 * 4096);
    const float4* os4 = (const float4*)OS;
#pragma unroll
    for (int i = tid; i < 2048; i += 256) og[i] = os4[i];
}

extern "C" void kernel_launch(void* const* d_in, const int* in_sizes, int n_in,
                              void* d_out, int out_size) {
    const float* x  = (const float*)d_in[0];
    const float* Wk = (const float*)d_in[1];
    const float* Wq = (const float*)d_in[2];
    const float* Wv = (const float*)d_in[3];
    float* out = (float*)d_out;

    cudaFuncSetAttribute(head_main, cudaFuncAttributeMaxDynamicSharedMemorySize, SMEM_BYTES);

    prep_weights<<<(CCH * NK + 255) / 256, 256>>>(Wk, Wq, Wv);
    head_main<<<BT / BPB, 256, SMEM_BYTES>>>(x, out);
}

// round 4
// speedup vs baseline: 1.7327x; 1.7327x over previous
#include <cuda_runtime.h>
#include <cuda_fp16.h>
#include <cstdint>

#define CCH 768
#define NK  192
#define NCHUNK 12
#define NT 512

// smem (bytes):
//  projection: XH fp16 [128][72] @0 (18432); W bufs @18432, per buf 51200 (hi 25600, lo 25600)
//              -> end 120832
//  attention overlay: KS/QS/VS/PS fp32, each 2*64*65*4 = 33280 -> 133120 total
#define WOFF(b) (18432 + (b) * 51200)
#define SMEM_BYTES 133120

__device__ __align__(16) __half g_Whi[CCH * NK];
__device__ __align__(16) __half g_Wlo[CCH * NK];

__global__ void prep_weights(const float* __restrict__ Wk,
                             const float* __restrict__ Wq,
                             const float* __restrict__ Wv) {
    int i = blockIdx.x * blockDim.x + threadIdx.x;
    if (i >= CCH * NK) return;
    int c = i / NK, n = i % NK;
    const float* W = (n < 64) ? Wk : (n < 128) ? Wq : Wv;
    float w = W[c * 64 + (n & 63)];
    __half h = __float2half_rn(w);
    g_Whi[i] = h;
    g_Wlo[i] = __float2half_rn(w - __half2float(h));
}

__device__ __forceinline__ uint32_t sptr(const void* p) {
    return (uint32_t)__cvta_generic_to_shared(p);
}
__device__ __forceinline__ void ldsm_x4(uint32_t* r, uint32_t addr) {
    asm volatile("ldmatrix.sync.aligned.m8n8.x4.shared.b16 {%0,%1,%2,%3}, [%4];"
                 : "=r"(r[0]), "=r"(r[1]), "=r"(r[2]), "=r"(r[3]) : "r"(addr));
}
__device__ __forceinline__ void ldsm_x4t(uint32_t* r, uint32_t addr) {
    asm volatile("ldmatrix.sync.aligned.m8n8.x4.trans.shared.b16 {%0,%1,%2,%3}, [%4];"
                 : "=r"(r[0]), "=r"(r[1]), "=r"(r[2]), "=r"(r[3]) : "r"(addr));
}
__device__ __forceinline__ void mma16816(float* c, const uint32_t* a, const uint32_t* b) {
    asm volatile("mma.sync.aligned.m16n8k16.row.col.f32.f16.f16.f32 "
                 "{%0,%1,%2,%3}, {%4,%5,%6,%7}, {%8,%9}, {%0,%1,%2,%3};"
                 : "+f"(c[0]), "+f"(c[1]), "+f"(c[2]), "+f"(c[3])
                 : "r"(a[0]), "r"(a[1]), "r"(a[2]), "r"(a[3]), "r"(b[0]), "r"(b[1]));
}
__device__ __forceinline__ void cpasync16(uint32_t d, const void* s) {
    asm volatile("cp.async.cg.shared.global [%0], [%1], 16;" :: "r"(d), "l"(s));
}

extern "C" __global__ void __launch_bounds__(NT, 1)
head_main(const float* __restrict__ x, float* __restrict__ out) {
    extern __shared__ char smem[];
    __half* XH = (__half*)smem;

    const int tid = threadIdx.x;
    const int w = tid >> 5;
    const int lane = tid & 31;

    const float* xb = x + (size_t)blockIdx.x * 128 * CCH;

    // -------- prefetch x chunk 0: 128 rows x 16 float4; 4 float4/thread
    float4 xr[4];
#pragma unroll
    for (int i = 0; i < 4; i++) {
        int idx = i * NT + tid;
        xr[i] = *(const float4*)(xb + (idx >> 4) * CCH + (idx & 15) * 4);
    }

    // -------- issue W chunk 0 -> buf 0
#pragma unroll
    for (int j = 0; j < 3; j++) {
        int idx = j * NT + tid;                 // 1536: 64 k-rows x 24 16B-segs
        int row = idx / 24, c16 = (idx % 24) * 8;
        uint32_t dh = sptr(smem + WOFF(0)) + (uint32_t)(row * 400 + c16 * 2);
        cpasync16(dh, g_Whi + row * NK + c16);
        cpasync16(dh + 25600, g_Wlo + row * NK + c16);
    }
    asm volatile("cp.async.commit_group;" ::: "memory");

    float acc[12][4];
#pragma unroll
    for (int jt = 0; jt < 12; jt++)
#pragma unroll
        for (int r = 0; r < 4; r++) acc[jt][r] = 0.0f;

    const int mw = w & 7;                       // M-tile (16 rows)
    const int nh = w >> 3;                      // N-half (96 cols)
    const int a_off = (16 * mw + (lane & 15)) * 72 + (lane >> 4) * 8;
    const int b_row = lane & 15;
    const int b_col = nh * 96 + (lane >> 4) * 8;

#pragma unroll 1
    for (int kc = 0; kc < NCHUNK; kc++) {
        const int buf = kc & 1;
        __syncthreads();  // prev chunk's MMA reads of XH and W[buf^1] complete

        if (kc + 1 < NCHUNK) {
            const size_t gk = (size_t)(kc + 1) * 64 * NK;
#pragma unroll
            for (int j = 0; j < 3; j++) {
                int idx = j * NT + tid;
                int row = idx / 24, c16 = (idx % 24) * 8;
                uint32_t dh = sptr(smem + WOFF(buf ^ 1)) + (uint32_t)(row * 400 + c16 * 2);
                cpasync16(dh, g_Whi + gk + row * NK + c16);
                cpasync16(dh + 25600, g_Wlo + gk + row * NK + c16);
            }
            asm volatile("cp.async.commit_group;" ::: "memory");
        }

        // x regs -> XH fp16 (single rounding)
#pragma unroll
        for (int i = 0; i < 4; i++) {
            int idx = i * NT + tid;
            int r = idx >> 4, s = idx & 15;
            float4 v = xr[i];
            __half2 h01 = __floats2half2_rn(v.x, v.y);
            __half2 h23 = __floats2half2_rn(v.z, v.w);
            uint2 pkt;
            pkt.x = *(uint32_t*)&h01;
            pkt.y = *(uint32_t*)&h23;
            *(uint2*)((char*)XH + (uint32_t)(r * 144 + s * 8)) = pkt;
        }

        if (kc + 1 < NCHUNK) asm volatile("cp.async.wait_group 1;" ::: "memory");
        else                 asm volatile("cp.async.wait_group 0;" ::: "memory");
        __syncthreads();  // XH + W[buf] visible to all

        // prefetch next x chunk
        if (kc + 1 < NCHUNK) {
#pragma unroll
            for (int i = 0; i < 4; i++) {
                int idx = i * NT + tid;
                xr[i] = *(const float4*)(xb + (idx >> 4) * CCH + (kc + 1) * 64 + (idx & 15) * 4);
            }
        }

        const __half* WHs = (const __half*)(smem + WOFF(buf));
        const __half* WLs = WHs + 12800;

#pragma unroll
        for (int ks = 0; ks < 4; ks++) {
            uint32_t ah[4];
            ldsm_x4(ah, sptr(XH + a_off + ks * 16));
            const int br = (ks * 16 + b_row) * 200 + b_col;
#pragma unroll
            for (int j = 0; j < 6; j++) {
                uint32_t bh[4], bl[4];
                ldsm_x4t(bh, sptr(WHs + br + j * 16));
                ldsm_x4t(bl, sptr(WLs + br + j * 16));
                mma16816(acc[2 * j],     ah, bh);
                mma16816(acc[2 * j + 1], ah, bh + 2);
                mma16816(acc[2 * j],     ah, bl);
                mma16816(acc[2 * j + 1], ah, bl + 2);
            }
        }
    }
    __syncthreads();  // projection done; smem repurposed

    // -------- fragments -> KS/QS/VS (fp32, row pad 65)
    float* KS = (float*)smem;
    float* QS = KS + 8320;
    float* VS = QS + 8320;
    float* PS = VS + 8320;
    {
        const int t0 = mw * 16 + (lane >> 2);
        const int bbx = t0 >> 6, tr = t0 & 63;
        const int c2 = (lane & 3) * 2;
#pragma unroll
        for (int jt = 0; jt < 12; jt++) {
            int col = nh * 96 + jt * 8 + c2;
            float* dst = (col < 64) ? (KS + col) : (col < 128) ? (QS + col - 64) : (VS + col - 128);
            float* p0 = dst + bbx * 4160 + tr * 65;
            p0[0] = acc[jt][0];
            p0[1] = acc[jt][1];
            p0[8 * 65] = acc[jt][2];
            p0[8 * 65 + 1] = acc[jt][3];
        }
    }
    __syncthreads();

    // -------- S = q k^T * 0.125, causal softmax (fp32, 2x8 microtile per lane)
    const int bb = w >> 3;             // batch (8 warps each)
    const int i0 = (w & 7) * 8;        // 8 token rows per warp
    const int li = lane >> 3, lj = lane & 7;
    const float* qrow = QS + bb * 4160;
    const float* krow = KS + bb * 4160;

    float s[2][8];
#pragma unroll
    for (int t = 0; t < 2; t++)
#pragma unroll
        for (int m = 0; m < 8; m++) s[t][m] = 0.0f;

#pragma unroll 4
    for (int c = 0; c < 64; c++) {
        float qv[2], kv[8];
#pragma unroll
        for (int t = 0; t < 2; t++) qv[t] = qrow[(i0 + li + 4 * t) * 65 + c];
#pragma unroll
        for (int m = 0; m < 8; m++) kv[m] = krow[(lj + 8 * m) * 65 + c];
#pragma unroll
        for (int t = 0; t < 2; t++)
#pragma unroll
            for (int m = 0; m < 8; m++) s[t][m] += qv[t] * kv[m];
    }

#pragma unroll
    for (int t = 0; t < 2; t++) {
        const int row = i0 + li + 4 * t;
        float mt = -3.0e38f;
#pragma unroll
        for (int m = 0; m < 8; m++) {
            int col = lj + 8 * m;
            float v = s[t][m] * 0.125f;
            v = (col <= row) ? v : -3.0e38f;
            s[t][m] = v;
            mt = fmaxf(mt, v);
        }
        mt = fmaxf(mt, __shfl_xor_sync(0xffffffffu, mt, 1));
        mt = fmaxf(mt, __shfl_xor_sync(0xffffffffu, mt, 2));
        mt = fmaxf(mt, __shfl_xor_sync(0xffffffffu, mt, 4));
        float sum = 0.0f;
#pragma unroll
        for (int m = 0; m < 8; m++) {
            float e = __expf(s[t][m] - mt);
            s[t][m] = e;
            sum += e;
        }
        sum += __shfl_xor_sync(0xffffffffu, sum, 1);
        sum += __shfl_xor_sync(0xffffffffu, sum, 2);
        sum += __shfl_xor_sync(0xffffffffu, sum, 4);
        float inv = 1.0f / sum;
#pragma unroll
        for (int m = 0; m < 8; m++)
            PS[bb * 4160 + row * 65 + lj + 8 * m] = s[t][m] * inv;
    }
    __syncthreads();

    // -------- out = P @ v
    float o[2][8];
#pragma unroll
    for (int t = 0; t < 2; t++)
#pragma unroll
        for (int m = 0; m < 8; m++) o[t][m] = 0.0f;

    const float* prow = PS + bb * 4160;
    const float* vrow = VS + bb * 4160;
#pragma unroll 4
    for (int cs = 0; cs < 64; cs++) {
        float pv[2], vv[8];
#pragma unroll
        for (int t = 0; t < 2; t++) pv[t] = prow[(i0 + li + 4 * t) * 65 + cs];
#pragma unroll
        for (int m = 0; m < 8; m++) vv[m] = vrow[cs * 65 + lj + 8 * m];
#pragma unroll
        for (int t = 0; t < 2; t++)
#pragma unroll
            for (int m = 0; m < 8; m++) o[t][m] += pv[t] * vv[m];
    }
    __syncthreads();  // PS reads done -> reuse as staging

    float* OS = PS;  // [2][64][64]
#pragma unroll
    for (int t = 0; t < 2; t++)
#pragma unroll
        for (int m = 0; m < 8; m++)
            OS[bb * 4096 + (i0 + li + 4 * t) * 64 + lj + 8 * m] = o[t][m];
    __syncthreads();

    float4* og = (float4*)(out + (size_t)blockIdx.x * 8192);
    const float4* os4 = (const float4*)OS;
#pragma unroll
    for (int i = tid; i < 2048; i += NT) og[i] = os4[i];
}

extern "C" void kernel_launch(void* const* d_in, const int* in_sizes, int n_in,
                              void* d_out, int out_size) {
    const float* x  = (const float*)d_in[0];
    const float* Wk = (const float*)d_in[1];
    const float* Wq = (const float*)d_in[2];
    const float* Wv = (const float*)d_in[3];
    float* out = (float*)d_out;

    cudaFuncSetAttribute(head_main, cudaFuncAttributeMaxDynamicSharedMemorySize, SMEM_BYTES);

    prep_weights<<<(CCH * NK + 255) / 256, 256>>>(Wk, Wq, Wv);
    head_main<<<1024, NT, SMEM_BYTES>>>(x, out);
}

// round 5
// speedup vs baseline: 1.8509x; 1.0682x over previous
#include <cuda_runtime.h>
#include <cuda_fp16.h>
#include <cstdint>

#define CCH 768
#define NK  192
#define NCHUNK 12
#define NT 512

// smem (bytes):
//  projection: XH fp16 [128][72] @0 (18432); W bufs @18432, per buf 51200 (hi 25600, lo 25600)
//              -> end 120832
//  attention overlay: KS/QS/VS/PS fp32, each 2*64*65*4 = 33280 -> 133120 total
#define WOFF(b) (18432 + (b) * 51200)
#define SMEM_BYTES 133120

__device__ __align__(16) __half g_Whi[CCH * NK];
__device__ __align__(16) __half g_Wlo[CCH * NK];

__global__ void prep_weights(const float* __restrict__ Wk,
                             const float* __restrict__ Wq,
                             const float* __restrict__ Wv) {
    int i = blockIdx.x * blockDim.x + threadIdx.x;
    if (i >= CCH * NK) return;
    int c = i / NK, n = i % NK;
    const float* W = (n < 64) ? Wk : (n < 128) ? Wq : Wv;
    float w = W[c * 64 + (n & 63)];
    __half h = __float2half_rn(w);
    g_Whi[i] = h;
    g_Wlo[i] = __float2half_rn(w - __half2float(h));
}

__device__ __forceinline__ uint32_t sptr(const void* p) {
    return (uint32_t)__cvta_generic_to_shared(p);
}
__device__ __forceinline__ void ldsm_x4(uint32_t* r, uint32_t addr) {
    asm volatile("ldmatrix.sync.aligned.m8n8.x4.shared.b16 {%0,%1,%2,%3}, [%4];"
                 : "=r"(r[0]), "=r"(r[1]), "=r"(r[2]), "=r"(r[3]) : "r"(addr));
}
__device__ __forceinline__ void ldsm_x4t(uint32_t* r, uint32_t addr) {
    asm volatile("ldmatrix.sync.aligned.m8n8.x4.trans.shared.b16 {%0,%1,%2,%3}, [%4];"
                 : "=r"(r[0]), "=r"(r[1]), "=r"(r[2]), "=r"(r[3]) : "r"(addr));
}
__device__ __forceinline__ void mma16816(float* c, const uint32_t* a, const uint32_t* b) {
    asm volatile("mma.sync.aligned.m16n8k16.row.col.f32.f16.f16.f32 "
                 "{%0,%1,%2,%3}, {%4,%5,%6,%7}, {%8,%9}, {%0,%1,%2,%3};"
                 : "+f"(c[0]), "+f"(c[1]), "+f"(c[2]), "+f"(c[3])
                 : "r"(a[0]), "r"(a[1]), "r"(a[2]), "r"(a[3]), "r"(b[0]), "r"(b[1]));
}
__device__ __forceinline__ void cpasync16(uint32_t d, const void* s) {
    asm volatile("cp.async.cg.shared.global [%0], [%1], 16;" :: "r"(d), "l"(s));
}

extern "C" __global__ void __launch_bounds__(NT, 1)
head_main(const float* __restrict__ x, float* __restrict__ out) {
    extern __shared__ char smem[];
    __half* XH = (__half*)smem;

    const int tid = threadIdx.x;
    const int w = tid >> 5;
    const int lane = tid & 31;

    const float* xb = x + (size_t)blockIdx.x * 128 * CCH;

    // -------- prefetch x chunk 0: 128 rows x 16 float4; 4 float4/thread
    float4 xr[4];
#pragma unroll
    for (int i = 0; i < 4; i++) {
        int idx = i * NT + tid;
        xr[i] = *(const float4*)(xb + (idx >> 4) * CCH + (idx & 15) * 4);
    }

    // -------- issue W chunk 0 -> buf 0
#pragma unroll
    for (int j = 0; j < 3; j++) {
        int idx = j * NT + tid;                 // 1536: 64 k-rows x 24 16B-segs
        int row = idx / 24, c16 = (idx % 24) * 8;
        uint32_t dh = sptr(smem + WOFF(0)) + (uint32_t)(row * 400 + c16 * 2);
        cpasync16(dh, g_Whi + row * NK + c16);
        cpasync16(dh + 25600, g_Wlo + row * NK + c16);
    }
    asm volatile("cp.async.commit_group;" ::: "memory");

    // warp grid 4x4: M32 x N48 per warp
    const int mwarp = w & 3;                    // M tile of 32 rows
    const int nwarp = w >> 2;                   // N tile of 48 cols

    float acc[12][4];                           // [mt*6 + jn][4], mt<2, jn<6
#pragma unroll
    for (int jt = 0; jt < 12; jt++)
#pragma unroll
        for (int r = 0; r < 4; r++) acc[jt][r] = 0.0f;

    const int a_base = (mwarp * 32 + (lane & 15)) * 72 + (lane >> 4) * 8;  // halves
    const int b_base = nwarp * 48 + (lane >> 4) * 8;                       // col part
    const int b_row = lane & 15;

#pragma unroll 1
    for (int kc = 0; kc < NCHUNK; kc++) {
        const int buf = kc & 1;
        __syncthreads();  // prev chunk's MMA reads of XH and W[buf^1] complete

        if (kc + 1 < NCHUNK) {
            const size_t gk = (size_t)(kc + 1) * 64 * NK;
#pragma unroll
            for (int j = 0; j < 3; j++) {
                int idx = j * NT + tid;
                int row = idx / 24, c16 = (idx % 24) * 8;
                uint32_t dh = sptr(smem + WOFF(buf ^ 1)) + (uint32_t)(row * 400 + c16 * 2);
                cpasync16(dh, g_Whi + gk + row * NK + c16);
                cpasync16(dh + 25600, g_Wlo + gk + row * NK + c16);
            }
            asm volatile("cp.async.commit_group;" ::: "memory");
        }

        // x regs -> XH fp16 (single rounding)
#pragma unroll
        for (int i = 0; i < 4; i++) {
            int idx = i * NT + tid;
            int r = idx >> 4, s = idx & 15;
            float4 v = xr[i];
            __half2 h01 = __floats2half2_rn(v.x, v.y);
            __half2 h23 = __floats2half2_rn(v.z, v.w);
            uint2 pkt;
            pkt.x = *(uint32_t*)&h01;
            pkt.y = *(uint32_t*)&h23;
            *(uint2*)((char*)XH + (uint32_t)(r * 144 + s * 8)) = pkt;
        }

        if (kc + 1 < NCHUNK) asm volatile("cp.async.wait_group 1;" ::: "memory");
        else                 asm volatile("cp.async.wait_group 0;" ::: "memory");
        __syncthreads();  // XH + W[buf] visible to all

        // prefetch next x chunk
        if (kc + 1 < NCHUNK) {
#pragma unroll
            for (int i = 0; i < 4; i++) {
                int idx = i * NT + tid;
                xr[i] = *(const float4*)(xb + (idx >> 4) * CCH + (kc + 1) * 64 + (idx & 15) * 4);
            }
        }

        const __half* WHs = (const __half*)(smem + WOFF(buf));
        const __half* WLs = WHs + 12800;

#pragma unroll
        for (int ks = 0; ks < 4; ks++) {
            uint32_t ah0[4], ah1[4];
            ldsm_x4(ah0, sptr(XH + a_base + ks * 16));
            ldsm_x4(ah1, sptr(XH + a_base + 16 * 72 + ks * 16));
            const int br = (ks * 16 + b_row) * 200 + b_base;
#pragma unroll
            for (int j = 0; j < 3; j++) {
                uint32_t bh[4], bl[4];
                ldsm_x4t(bh, sptr(WHs + br + j * 16));
                ldsm_x4t(bl, sptr(WLs + br + j * 16));
                // hi pass: 4 independent acc chains, then lo pass
                mma16816(acc[0 * 6 + 2 * j],     ah0, bh);
                mma16816(acc[0 * 6 + 2 * j + 1], ah0, bh + 2);
                mma16816(acc[1 * 6 + 2 * j],     ah1, bh);
                mma16816(acc[1 * 6 + 2 * j + 1], ah1, bh + 2);
                mma16816(acc[0 * 6 + 2 * j],     ah0, bl);
                mma16816(acc[0 * 6 + 2 * j + 1], ah0, bl + 2);
                mma16816(acc[1 * 6 + 2 * j],     ah1, bl);
                mma16816(acc[1 * 6 + 2 * j + 1], ah1, bl + 2);
            }
        }
    }
    __syncthreads();  // projection done; smem repurposed

    // -------- fragments -> KS/QS/VS (fp32, row pad 65)
    float* KS = (float*)smem;
    float* QS = KS + 8320;
    float* VS = QS + 8320;
    float* PS = VS + 8320;
    {
        const int c2 = (lane & 3) * 2;
#pragma unroll
        for (int mt = 0; mt < 2; mt++) {
            const int t0 = mwarp * 32 + mt * 16 + (lane >> 2);
            const int bbx = t0 >> 6, tr = t0 & 63;
#pragma unroll
            for (int jn = 0; jn < 6; jn++) {
                int col = nwarp * 48 + jn * 8 + c2;
                float* dst = (col < 64) ? (KS + col) : (col < 128) ? (QS + col - 64) : (VS + col - 128);
                float* p0 = dst + bbx * 4160 + tr * 65;
                const float* a = acc[mt * 6 + jn];
                p0[0] = a[0];
                p0[1] = a[1];
                p0[8 * 65] = a[2];
                p0[8 * 65 + 1] = a[3];
            }
        }
    }
    __syncthreads();

    // -------- S = q k^T * 0.125, causal softmax (fp32, 2x8 microtile per lane)
    const int bb = w >> 3;             // batch (8 warps each)
    const int i0 = (w & 7) * 8;        // 8 token rows per warp
    const int li = lane >> 3, lj = lane & 7;
    const float* qrow = QS + bb * 4160;
    const float* krow = KS + bb * 4160;

    float s[2][8];
#pragma unroll
    for (int t = 0; t < 2; t++)
#pragma unroll
        for (int m = 0; m < 8; m++) s[t][m] = 0.0f;

#pragma unroll 4
    for (int c = 0; c < 64; c++) {
        float qv[2], kv[8];
#pragma unroll
        for (int t = 0; t < 2; t++) qv[t] = qrow[(i0 + li + 4 * t) * 65 + c];
#pragma unroll
        for (int m = 0; m < 8; m++) kv[m] = krow[(lj + 8 * m) * 65 + c];
#pragma unroll
        for (int t = 0; t < 2; t++)
#pragma unroll
            for (int m = 0; m < 8; m++) s[t][m] += qv[t] * kv[m];
    }

#pragma unroll
    for (int t = 0; t < 2; t++) {
        const int row = i0 + li + 4 * t;
        float mt = -3.0e38f;
#pragma unroll
        for (int m = 0; m < 8; m++) {
            int col = lj + 8 * m;
            float v = s[t][m] * 0.125f;
            v = (col <= row) ? v : -3.0e38f;
            s[t][m] = v;
            mt = fmaxf(mt, v);
        }
        mt = fmaxf(mt, __shfl_xor_sync(0xffffffffu, mt, 1));
        mt = fmaxf(mt, __shfl_xor_sync(0xffffffffu, mt, 2));
        mt = fmaxf(mt, __shfl_xor_sync(0xffffffffu, mt, 4));
        float sum = 0.0f;
#pragma unroll
        for (int m = 0; m < 8; m++) {
            float e = __expf(s[t][m] - mt);
            s[t][m] = e;
            sum += e;
        }
        sum += __shfl_xor_sync(0xffffffffu, sum, 1);
        sum += __shfl_xor_sync(0xffffffffu, sum, 2);
        sum += __shfl_xor_sync(0xffffffffu, sum, 4);
        float inv = 1.0f / sum;
#pragma unroll
        for (int m = 0; m < 8; m++)
            PS[bb * 4160 + row * 65 + lj + 8 * m] = s[t][m] * inv;
    }
    __syncthreads();

    // -------- out = P @ v
    float o[2][8];
#pragma unroll
    for (int t = 0; t < 2; t++)
#pragma unroll
        for (int m = 0; m < 8; m++) o[t][m] = 0.0f;

    const float* prow = PS + bb * 4160;
    const float* vrow = VS + bb * 4160;
#pragma unroll 4
    for (int cs = 0; cs < 64; cs++) {
        float pv[2], vv[8];
#pragma unroll
        for (int t = 0; t < 2; t++) pv[t] = prow[(i0 + li + 4 * t) * 65 + cs];
#pragma unroll
        for (int m = 0; m < 8; m++) vv[m] = vrow[cs * 65 + lj + 8 * m];
#pragma unroll
        for (int t = 0; t < 2; t++)
#pragma unroll
            for (int m = 0; m < 8; m++) o[t][m] += pv[t] * vv[m];
    }
    __syncthreads();  // PS reads done -> reuse as staging

    float* OS = PS;  // [2][64][64]
#pragma unroll
    for (int t = 0; t < 2; t++)
#pragma unroll
        for (int m = 0; m < 8; m++)
            OS[bb * 4096 + (i0 + li + 4 * t) * 64 + lj + 8 * m] = o[t][m];
    __syncthreads();

    float4* og = (float4*)(out + (size_t)blockIdx.x * 8192);
    const float4* os4 = (const float4*)OS;
#pragma unroll
    for (int i = tid; i < 2048; i += NT) og[i] = os4[i];
}

extern "C" void kernel_launch(void* const* d_in, const int* in_sizes, int n_in,
                              void* d_out, int out_size) {
    const float* x  = (const float*)d_in[0];
    const float* Wk = (const float*)d_in[1];
    const float* Wq = (const float*)d_in[2];
    const float* Wv = (const float*)d_in[3];
    float* out = (float*)d_out;

    cudaFuncSetAttribute(head_main, cudaFuncAttributeMaxDynamicSharedMemorySize, SMEM_BYTES);

    prep_weights<<<(CCH * NK + 255) / 256, 256>>>(Wk, Wq, Wv);
    head_main<<<1024, NT, SMEM_BYTES>>>(x, out);
}